// round 1
// baseline (speedup 1.0000x reference)
#include <cuda_runtime.h>

#define TT 2048
#define BB 4
#define HH 16
#define GG 4
#define DD 64
#define EMB 1024

// Scratch (device globals; no allocation allowed)
__device__ float g_q[(size_t)BB * HH * TT * DD];     // [B,H,T,64]
__device__ float g_k[(size_t)BB * GG * TT * DD];     // [B,G,T,64]
__device__ float g_v[(size_t)BB * GG * TT * DD];     // [B,G,T,64]
__device__ float g_attn[(size_t)BB * TT * EMB];      // [B,T,1024] head-major concat

// ---------------------------------------------------------------------------
// SGEMM: C = A[M,1024] @ Bm[N,1024]^T, epilogue scatter by mode.
// mode 0: scatter to q layout [B,H,T,64]
// mode 1: scatter to k/v layout [B,G,T,64]
// mode 2: plain row-major [M,1024] + bias
// BM=BN=128, BK=8, 256 threads, 8x8 microtile (split 4+4 for conflict-free LDS)
// ---------------------------------------------------------------------------
__global__ __launch_bounds__(256) void sgemm_kernel(
    const float* __restrict__ A, const float* __restrict__ Bm,
    float* __restrict__ Cout, int mode, const float* __restrict__ bias)
{
    __shared__ float As[8][128];
    __shared__ float Bs[8][128];

    const int tid = threadIdx.x;
    const int tx = tid & 15;
    const int ty = tid >> 4;
    const int m0 = blockIdx.y * 128;
    const int n0 = blockIdx.x * 128;

    const int lr = tid >> 1;        // 0..127
    const int lc = (tid & 1) * 4;   // 0 or 4
    const float* Aptr = A + (size_t)(m0 + lr) * 1024 + lc;
    const float* Bptr = Bm + (size_t)(n0 + lr) * 1024 + lc;

    float acc[8][8];
#pragma unroll
    for (int i = 0; i < 8; i++)
#pragma unroll
        for (int j = 0; j < 8; j++) acc[i][j] = 0.f;

    for (int k0 = 0; k0 < 1024; k0 += 8) {
        float4 av = *(const float4*)(Aptr + k0);
        float4 bv = *(const float4*)(Bptr + k0);
        __syncthreads();
        As[lc + 0][lr] = av.x; As[lc + 1][lr] = av.y;
        As[lc + 2][lr] = av.z; As[lc + 3][lr] = av.w;
        Bs[lc + 0][lr] = bv.x; Bs[lc + 1][lr] = bv.y;
        Bs[lc + 2][lr] = bv.z; Bs[lc + 3][lr] = bv.w;
        __syncthreads();
#pragma unroll
        for (int kk = 0; kk < 8; kk++) {
            float4 a0 = *(const float4*)&As[kk][ty * 4];
            float4 a1 = *(const float4*)&As[kk][64 + ty * 4];
            float4 b0 = *(const float4*)&Bs[kk][tx * 4];
            float4 b1 = *(const float4*)&Bs[kk][64 + tx * 4];
            float a[8] = {a0.x, a0.y, a0.z, a0.w, a1.x, a1.y, a1.z, a1.w};
            float b[8] = {b0.x, b0.y, b0.z, b0.w, b1.x, b1.y, b1.z, b1.w};
#pragma unroll
            for (int i = 0; i < 8; i++)
#pragma unroll
                for (int j = 0; j < 8; j++)
                    acc[i][j] += a[i] * b[j];
        }
    }

#pragma unroll
    for (int i = 0; i < 8; i++) {
        int r = m0 + ((i < 4) ? (ty * 4 + i) : (64 + ty * 4 + i - 4));
#pragma unroll
        for (int j = 0; j < 8; j++) {
            int c = n0 + ((j < 4) ? (tx * 4 + j) : (64 + tx * 4 + j - 4));
            float v = acc[i][j];
            if (mode == 0) {
                // q: [B,H,T,64]; r = b*T+t, c = h*64+d
                int b = r >> 11, t = r & 2047, h = c >> 6, d = c & 63;
                Cout[(((size_t)(b * 16 + h) * 2048) + t) * 64 + d] = v;
            } else if (mode == 1) {
                int b = r >> 11, t = r & 2047, g = c >> 6, d = c & 63;
                Cout[(((size_t)(b * 4 + g) * 2048) + t) * 64 + d] = v;
            } else {
                Cout[(size_t)r * 1024 + c] = v + bias[c];
            }
        }
    }
}

// ---------------------------------------------------------------------------
// Flash attention, fp32, causal. One thread owns one query row.
// Block = 128 threads = 128 query rows; K/V tiles of 64 keys in shared.
// Online softmax in 32-key chunks (register budget).
// ---------------------------------------------------------------------------
__global__ __launch_bounds__(128) void attn_kernel(float* __restrict__ out)
{
    __shared__ float Ks[64 * 64];
    __shared__ float Vs[64 * 64];

    const int tid = threadIdx.x;
    const int q0 = blockIdx.x * 128;
    const int bh = blockIdx.y;
    const int b = bh >> 4;
    const int h = bh & 15;
    const int g = h >> 2;     // GROUP_SIZE = 4
    const int qi = q0 + tid;

    const float* qptr = g_q + ((size_t)(b * 16 + h) * TT + qi) * 64;
    float q[64];
#pragma unroll
    for (int d4 = 0; d4 < 16; d4++) {
        float4 v = ((const float4*)qptr)[d4];
        q[4 * d4] = v.x; q[4 * d4 + 1] = v.y; q[4 * d4 + 2] = v.z; q[4 * d4 + 3] = v.w;
    }

    float o[64];
#pragma unroll
    for (int d = 0; d < 64; d++) o[d] = 0.f;
    float m = -1e30f, l = 0.f;

    const float* kbase = g_k + (size_t)(b * 4 + g) * TT * 64;
    const float* vbase = g_v + (size_t)(b * 4 + g) * TT * 64;
    const float scale = 0.125f;  // 64^-0.5

    const int nkt = q0 / 64 + 2;  // key tiles covering [0, q0+128)
    for (int kt = 0; kt < nkt; kt++) {
        __syncthreads();
        const float4* kg = (const float4*)(kbase + (size_t)kt * 64 * 64);
        const float4* vg = (const float4*)(vbase + (size_t)kt * 64 * 64);
#pragma unroll
        for (int i = 0; i < 8; i++) {
            int idx = i * 128 + tid;
            ((float4*)Ks)[idx] = kg[idx];
            ((float4*)Vs)[idx] = vg[idx];
        }
        __syncthreads();

        const int kb = kt * 64;
        if (qi < kb) continue;  // this thread fully masked for this tile

        for (int jc = 0; jc < 64; jc += 32) {
            if (qi < kb + jc) break;  // chunk fully masked
            float s[32];
            float mt = -1e30f;
#pragma unroll
            for (int j = 0; j < 32; j++) {
                const float4* krow = (const float4*)(Ks + (jc + j) * 64);
                float a = 0.f;
#pragma unroll
                for (int d4 = 0; d4 < 16; d4++) {
                    float4 kv = krow[d4];
                    a += q[4 * d4] * kv.x + q[4 * d4 + 1] * kv.y
                       + q[4 * d4 + 2] * kv.z + q[4 * d4 + 3] * kv.w;
                }
                s[j] = (kb + jc + j <= qi) ? a * scale : -1e30f;
                mt = fmaxf(mt, s[j]);
            }
            float mn = fmaxf(m, mt);
            float corr = __expf(m - mn);
            l *= corr;
#pragma unroll
            for (int d = 0; d < 64; d++) o[d] *= corr;
#pragma unroll
            for (int j = 0; j < 32; j++) {
                float p = __expf(s[j] - mn);
                l += p;
                const float4* vrow = (const float4*)(Vs + (jc + j) * 64);
#pragma unroll
                for (int d4 = 0; d4 < 16; d4++) {
                    float4 vv = vrow[d4];
                    o[4 * d4]     += p * vv.x;
                    o[4 * d4 + 1] += p * vv.y;
                    o[4 * d4 + 2] += p * vv.z;
                    o[4 * d4 + 3] += p * vv.w;
                }
            }
            m = mn;
        }
    }

    const float inv = 1.f / l;
    float* optr = out + (((size_t)(b * TT + qi) * 16) + h) * 64;
#pragma unroll
    for (int d4 = 0; d4 < 16; d4++) {
        float4 v;
        v.x = o[4 * d4] * inv; v.y = o[4 * d4 + 1] * inv;
        v.z = o[4 * d4 + 2] * inv; v.w = o[4 * d4 + 3] * inv;
        ((float4*)optr)[d4] = v;
    }
}

extern "C" void kernel_launch(void* const* d_in, const int* in_sizes, int n_in,
                              void* d_out, int out_size)
{
    const float* x  = (const float*)d_in[0];   // [4,2048,1024]
    const float* Wq = (const float*)d_in[1];   // [16,64,1024]
    const float* Wk = (const float*)d_in[2];   // [4,64,1024]
    const float* Wv = (const float*)d_in[3];   // [4,64,1024]
    const float* Wp = (const float*)d_in[4];   // [1024,1024]
    const float* bp = (const float*)d_in[5];   // [1024]
    float* out = (float*)d_out;

    float *gq, *gk, *gv, *gattn;
    cudaGetSymbolAddress((void**)&gq, g_q);
    cudaGetSymbolAddress((void**)&gk, g_k);
    cudaGetSymbolAddress((void**)&gv, g_v);
    cudaGetSymbolAddress((void**)&gattn, g_attn);

    // M = B*T = 8192 rows everywhere
    dim3 blk(256);
    sgemm_kernel<<<dim3(8, 64), blk>>>(x, Wq, gq, 0, nullptr);      // N=1024
    sgemm_kernel<<<dim3(2, 64), blk>>>(x, Wk, gk, 1, nullptr);      // N=256
    sgemm_kernel<<<dim3(2, 64), blk>>>(x, Wv, gv, 1, nullptr);      // N=256

    attn_kernel<<<dim3(16, 64), 128>>>(gattn);

    sgemm_kernel<<<dim3(8, 64), blk>>>(gattn, Wp, out, 2, bp);      // N=1024
}

// round 2
// speedup vs baseline: 2.8262x; 2.8262x over previous
#include <cuda_runtime.h>

#define TT 2048
#define BATCH 4

// Scratch (device globals; allocation is forbidden)
__device__ float g_q[(size_t)BATCH * TT * 1024];   // [b, t, h*64+d]
__device__ float g_k[(size_t)BATCH * TT * 256];    // [b, t, g*64+d]
__device__ float g_v[(size_t)BATCH * TT * 256];
__device__ float g_attn[(size_t)BATCH * TT * 1024];

__device__ __forceinline__ unsigned f2tf(float x) {
    unsigned r;
    asm("cvt.rna.tf32.f32 %0, %1;" : "=r"(r) : "f"(x));
    return r;
}

__device__ __forceinline__ void mma8(float* d,
                                     unsigned a0, unsigned a1, unsigned a2, unsigned a3,
                                     unsigned b0, unsigned b1) {
    asm volatile(
        "mma.sync.aligned.m16n8k8.row.col.f32.tf32.tf32.f32 "
        "{%0,%1,%2,%3},{%4,%5,%6,%7},{%8,%9},{%0,%1,%2,%3};"
        : "+f"(d[0]), "+f"(d[1]), "+f"(d[2]), "+f"(d[3])
        : "r"(a0), "r"(a1), "r"(a2), "r"(a3), "r"(b0), "r"(b1));
}

// Swizzled position of k-group j for (row, chunk). Returns float offset of the
// 4-float group within the 16-float row.
__device__ __forceinline__ int swzp(int row, int ch, int j) {
    return ((j ^ (row >> 1) ^ ch) & 3) * 4;
}

// ---------------------------------------------------------------------------
// tf32 GEMM: C[M,N] = A[M,1024] @ Bw[N,1024]^T (+bias). M=8192.
// Block 128x128, BK=16, 256 threads (8 warps, warp tile 64x32).
// ---------------------------------------------------------------------------
__global__ __launch_bounds__(256) void gemm_tf32(
    const float* __restrict__ A, const float* __restrict__ Bw,
    float* __restrict__ C, int N, const float* __restrict__ bias)
{
    __shared__ unsigned As[128][16];
    __shared__ unsigned Bs[128][16];

    const int tid = threadIdx.x;
    const int lane = tid & 31, warp = tid >> 5;
    const int gid = lane >> 2, tig = lane & 3;
    const int wm = warp >> 2, wn = warp & 3;       // 2 x 4 warp grid
    const int m0 = blockIdx.y * 128, n0 = blockIdx.x * 128;

    const int srow = tid >> 2;            // staging: 4 float4 per 16-float row
    const int sc = tid & 3;
    const int srow2 = srow + 64;

    float acc[4][4][4];
#pragma unroll
    for (int i = 0; i < 4; i++)
#pragma unroll
        for (int j = 0; j < 4; j++)
#pragma unroll
            for (int k = 0; k < 4; k++) acc[i][j][k] = 0.f;

    for (int k0 = 0; k0 < 1024; k0 += 16) {
        float4 av0 = *(const float4*)&A[(size_t)(m0 + srow) * 1024 + k0 + sc * 4];
        float4 av1 = *(const float4*)&A[(size_t)(m0 + srow2) * 1024 + k0 + sc * 4];
        float4 bv0 = *(const float4*)&Bw[(size_t)(n0 + srow) * 1024 + k0 + sc * 4];
        float4 bv1 = *(const float4*)&Bw[(size_t)(n0 + srow2) * 1024 + k0 + sc * 4];
        __syncthreads();
        As[srow][swzp(srow, 0, 0) + sc] = f2tf(av0.x);
        As[srow][swzp(srow, 0, 1) + sc] = f2tf(av0.y);
        As[srow][swzp(srow, 0, 2) + sc] = f2tf(av0.z);
        As[srow][swzp(srow, 0, 3) + sc] = f2tf(av0.w);
        As[srow2][swzp(srow2, 0, 0) + sc] = f2tf(av1.x);
        As[srow2][swzp(srow2, 0, 1) + sc] = f2tf(av1.y);
        As[srow2][swzp(srow2, 0, 2) + sc] = f2tf(av1.z);
        As[srow2][swzp(srow2, 0, 3) + sc] = f2tf(av1.w);
        Bs[srow][swzp(srow, 0, 0) + sc] = f2tf(bv0.x);
        Bs[srow][swzp(srow, 0, 1) + sc] = f2tf(bv0.y);
        Bs[srow][swzp(srow, 0, 2) + sc] = f2tf(bv0.z);
        Bs[srow][swzp(srow, 0, 3) + sc] = f2tf(bv0.w);
        Bs[srow2][swzp(srow2, 0, 0) + sc] = f2tf(bv1.x);
        Bs[srow2][swzp(srow2, 0, 1) + sc] = f2tf(bv1.y);
        Bs[srow2][swzp(srow2, 0, 2) + sc] = f2tf(bv1.z);
        Bs[srow2][swzp(srow2, 0, 3) + sc] = f2tf(bv1.w);
        __syncthreads();

        uint4 bfr[4];
#pragma unroll
        for (int nt = 0; nt < 4; nt++) {
            int rb = wn * 32 + nt * 8 + gid;
            bfr[nt] = *(const uint4*)&Bs[rb][swzp(rb, 0, tig)];
        }
#pragma unroll
        for (int mt = 0; mt < 4; mt++) {
            int r = wm * 64 + mt * 16 + gid;
            uint4 lo = *(const uint4*)&As[r][swzp(r, 0, tig)];
            uint4 hi = *(const uint4*)&As[r + 8][swzp(r + 8, 0, tig)];
#pragma unroll
            for (int nt = 0; nt < 4; nt++) {
                mma8(acc[mt][nt], lo.x, hi.x, lo.y, hi.y, bfr[nt].x, bfr[nt].y);
                mma8(acc[mt][nt], lo.z, hi.z, lo.w, hi.w, bfr[nt].z, bfr[nt].w);
            }
        }
    }

#pragma unroll
    for (int mt = 0; mt < 4; mt++) {
#pragma unroll
        for (int nt = 0; nt < 4; nt++) {
            int row = m0 + wm * 64 + mt * 16 + gid;
            int col = n0 + wn * 32 + nt * 8 + 2 * tig;
            float b0 = 0.f, b1 = 0.f;
            if (bias) { b0 = bias[col]; b1 = bias[col + 1]; }
            float2 v0 = make_float2(acc[mt][nt][0] + b0, acc[mt][nt][1] + b1);
            float2 v1 = make_float2(acc[mt][nt][2] + b0, acc[mt][nt][3] + b1);
            *(float2*)&C[(size_t)row * N + col] = v0;
            *(float2*)&C[(size_t)(row + 8) * N + col] = v1;
        }
    }
}

// ---------------------------------------------------------------------------
// Flash attention, tf32 mma. Block = one (b,h) x 64-query tile, 128 threads.
// S tile 64x64 per iteration; P reuses the K shared buffer.
// ---------------------------------------------------------------------------
__global__ __launch_bounds__(128) void attn_tf32(
    const float* __restrict__ qbuf, const float* __restrict__ kbuf,
    const float* __restrict__ vbuf, float* __restrict__ obuf)
{
    __shared__ unsigned Qs[4][64][16];   // 16KB
    __shared__ unsigned Ks[4][64][16];   // 16KB  (reused as P)
    __shared__ unsigned Vt[4][64][16];   // 16KB  (V transposed: [chunk][d][k-perm])

    const int tid = threadIdx.x;
    const int lane = tid & 31, warp = tid >> 5;
    const int gid = lane >> 2, tig = lane & 3;
    const int q0 = blockIdx.x * 64;
    const int bh = blockIdx.y;
    const int b = bh >> 4, h = bh & 15, g = h >> 2;

    const float* qb = qbuf + (size_t)b * TT * 1024 + h * 64;
    const float* kb = kbuf + (size_t)b * TT * 256 + g * 64;
    const float* vb = vbuf + (size_t)b * TT * 256 + g * 64;

    // Stage Q tile (64 rows x 64 cols), fold in softmax scale.
    const float SCALE = 0.125f;
#pragma unroll
    for (int i = 0; i < 8; i++) {
        int idx = i * 128 + tid;
        int row = idx >> 4, c4 = idx & 15;
        float4 f = *(const float4*)&qb[(size_t)(q0 + row) * 1024 + c4 * 4];
        int ch = c4 >> 2, cc = c4 & 3;
        Qs[ch][row][swzp(row, ch, 0) + cc] = f2tf(f.x * SCALE);
        Qs[ch][row][swzp(row, ch, 1) + cc] = f2tf(f.y * SCALE);
        Qs[ch][row][swzp(row, ch, 2) + cc] = f2tf(f.z * SCALE);
        Qs[ch][row][swzp(row, ch, 3) + cc] = f2tf(f.w * SCALE);
    }

    float o[8][4];
#pragma unroll
    for (int nt = 0; nt < 8; nt++)
#pragma unroll
        for (int k = 0; k < 4; k++) o[nt][k] = 0.f;
    float mrow0 = -1e30f, mrow1 = -1e30f, lrow0 = 0.f, lrow1 = 0.f;

    const int row0 = q0 + 16 * warp + gid;
    const int row1 = row0 + 8;
    const int rl = 16 * warp + gid;
    const int diag = q0 >> 6;

    for (int kt = 0; kt <= diag; kt++) {
        __syncthreads();   // protect Ks/Vt reuse from previous iteration
        // Stage K (row = key, coalesced)
#pragma unroll
        for (int i = 0; i < 8; i++) {
            int idx = i * 128 + tid;
            int row = idx >> 4, c4 = idx & 15;
            float4 f = *(const float4*)&kb[(size_t)(kt * 64 + row) * 256 + c4 * 4];
            int ch = c4 >> 2, cc = c4 & 3;
            Ks[ch][row][swzp(row, ch, 0) + cc] = f2tf(f.x);
            Ks[ch][row][swzp(row, ch, 1) + cc] = f2tf(f.y);
            Ks[ch][row][swzp(row, ch, 2) + cc] = f2tf(f.z);
            Ks[ch][row][swzp(row, ch, 3) + cc] = f2tf(f.w);
        }
        // Stage V transposed: Vt[chunk][d][k16-group]
#pragma unroll
        for (int i = 0; i < 8; i++) {
            int idx = i * 128 + tid;
            int t = idx & 63, c4 = idx >> 6;
            float4 f = *(const float4*)&vb[(size_t)(kt * 64 + t) * 256 + c4 * 4];
            int ch = t >> 4, k16 = t & 15;
            int jg = k16 & 3, cc = k16 >> 2;
            int d0 = c4 * 4;
            Vt[ch][d0 + 0][swzp(d0 + 0, ch, jg) + cc] = f2tf(f.x);
            Vt[ch][d0 + 1][swzp(d0 + 1, ch, jg) + cc] = f2tf(f.y);
            Vt[ch][d0 + 2][swzp(d0 + 2, ch, jg) + cc] = f2tf(f.z);
            Vt[ch][d0 + 3][swzp(d0 + 3, ch, jg) + cc] = f2tf(f.w);
        }
        __syncthreads();

        // S = Q @ K^T  (per warp: 16 rows x 64 cols)
        float s[8][4];
#pragma unroll
        for (int nt = 0; nt < 8; nt++)
#pragma unroll
            for (int k = 0; k < 4; k++) s[nt][k] = 0.f;
#pragma unroll
        for (int ch = 0; ch < 4; ch++) {
            uint4 lo = *(const uint4*)&Qs[ch][rl][swzp(rl, ch, tig)];
            uint4 hi = *(const uint4*)&Qs[ch][rl + 8][swzp(rl + 8, ch, tig)];
#pragma unroll
            for (int nt = 0; nt < 8; nt++) {
                int rbb = nt * 8 + gid;
                uint4 bf = *(const uint4*)&Ks[ch][rbb][swzp(rbb, ch, tig)];
                mma8(s[nt], lo.x, hi.x, lo.y, hi.y, bf.x, bf.y);
                mma8(s[nt], lo.z, hi.z, lo.w, hi.w, bf.z, bf.w);
            }
        }

        // Causal mask on the diagonal tile
        if (kt == diag) {
#pragma unroll
            for (int nt = 0; nt < 8; nt++) {
                int kcol = kt * 64 + nt * 8 + 2 * tig;
                if (kcol > row0) s[nt][0] = -1e30f;
                if (kcol + 1 > row0) s[nt][1] = -1e30f;
                if (kcol > row1) s[nt][2] = -1e30f;
                if (kcol + 1 > row1) s[nt][3] = -1e30f;
            }
        }

        // Online softmax (rows row0, row1; quad = lanes sharing gid)
        float mt0 = -1e30f, mt1 = -1e30f;
#pragma unroll
        for (int nt = 0; nt < 8; nt++) {
            mt0 = fmaxf(mt0, fmaxf(s[nt][0], s[nt][1]));
            mt1 = fmaxf(mt1, fmaxf(s[nt][2], s[nt][3]));
        }
        mt0 = fmaxf(mt0, __shfl_xor_sync(0xffffffffu, mt0, 1));
        mt0 = fmaxf(mt0, __shfl_xor_sync(0xffffffffu, mt0, 2));
        mt1 = fmaxf(mt1, __shfl_xor_sync(0xffffffffu, mt1, 1));
        mt1 = fmaxf(mt1, __shfl_xor_sync(0xffffffffu, mt1, 2));
        float mn0 = fmaxf(mrow0, mt0), mn1 = fmaxf(mrow1, mt1);
        float c0 = __expf(mrow0 - mn0), c1 = __expf(mrow1 - mn1);
        float ps0 = 0.f, ps1 = 0.f;
#pragma unroll
        for (int nt = 0; nt < 8; nt++) {
            s[nt][0] = __expf(s[nt][0] - mn0); ps0 += s[nt][0];
            s[nt][1] = __expf(s[nt][1] - mn0); ps0 += s[nt][1];
            s[nt][2] = __expf(s[nt][2] - mn1); ps1 += s[nt][2];
            s[nt][3] = __expf(s[nt][3] - mn1); ps1 += s[nt][3];
            o[nt][0] *= c0; o[nt][1] *= c0; o[nt][2] *= c1; o[nt][3] *= c1;
        }
        ps0 += __shfl_xor_sync(0xffffffffu, ps0, 1);
        ps0 += __shfl_xor_sync(0xffffffffu, ps0, 2);
        ps1 += __shfl_xor_sync(0xffffffffu, ps1, 1);
        ps1 += __shfl_xor_sync(0xffffffffu, ps1, 2);
        lrow0 = lrow0 * c0 + ps0;
        lrow1 = lrow1 * c1 + ps1;
        mrow0 = mn0; mrow1 = mn1;

        __syncthreads();   // all warps done reading Ks before P overwrite

        // Write P into Ks region, A-fragment permuted layout (k = key index)
#pragma unroll
        for (int nt = 0; nt < 8; nt++) {
            int c = nt * 8 + 2 * tig;
            int ch = c >> 4, c16 = c & 15;
            int jg = c16 & 3, cc = c16 >> 2;
            Ks[ch][rl][swzp(rl, ch, jg) + cc] = f2tf(s[nt][0]);
            Ks[ch][rl][swzp(rl, ch, jg + 1) + cc] = f2tf(s[nt][1]);
            Ks[ch][rl + 8][swzp(rl + 8, ch, jg) + cc] = f2tf(s[nt][2]);
            Ks[ch][rl + 8][swzp(rl + 8, ch, jg + 1) + cc] = f2tf(s[nt][3]);
        }
        __syncwarp();      // each warp reads back only its own rows

        // O += P @ V
#pragma unroll
        for (int ch = 0; ch < 4; ch++) {
            uint4 lo = *(const uint4*)&Ks[ch][rl][swzp(rl, ch, tig)];
            uint4 hi = *(const uint4*)&Ks[ch][rl + 8][swzp(rl + 8, ch, tig)];
#pragma unroll
            for (int nt = 0; nt < 8; nt++) {
                int rbb = nt * 8 + gid;
                uint4 bf = *(const uint4*)&Vt[ch][rbb][swzp(rbb, ch, tig)];
                mma8(o[nt], lo.x, hi.x, lo.y, hi.y, bf.x, bf.y);
                mma8(o[nt], lo.z, hi.z, lo.w, hi.w, bf.z, bf.w);
            }
        }
    }

    // Epilogue: normalize and write [b, t, h*64+d]
    const float i0 = 1.f / lrow0, i1 = 1.f / lrow1;
#pragma unroll
    for (int nt = 0; nt < 8; nt++) {
        int col = h * 64 + nt * 8 + 2 * tig;
        float2 v0 = make_float2(o[nt][0] * i0, o[nt][1] * i0);
        float2 v1 = make_float2(o[nt][2] * i1, o[nt][3] * i1);
        *(float2*)&obuf[((size_t)b * TT + row0) * 1024 + col] = v0;
        *(float2*)&obuf[((size_t)b * TT + row1) * 1024 + col] = v1;
    }
}

extern "C" void kernel_launch(void* const* d_in, const int* in_sizes, int n_in,
                              void* d_out, int out_size)
{
    const float* x  = (const float*)d_in[0];   // [4,2048,1024]
    const float* Wq = (const float*)d_in[1];   // [16,64,1024] -> [1024][1024]
    const float* Wk = (const float*)d_in[2];   // [4,64,1024]  -> [256][1024]
    const float* Wv = (const float*)d_in[3];
    const float* Wp = (const float*)d_in[4];   // [1024,1024]
    const float* bp = (const float*)d_in[5];   // [1024]
    float* out = (float*)d_out;

    float *gq, *gk, *gv, *gattn;
    cudaGetSymbolAddress((void**)&gq, g_q);
    cudaGetSymbolAddress((void**)&gk, g_k);
    cudaGetSymbolAddress((void**)&gv, g_v);
    cudaGetSymbolAddress((void**)&gattn, g_attn);

    gemm_tf32<<<dim3(8, 64), 256>>>(x, Wq, gq, 1024, nullptr);
    gemm_tf32<<<dim3(2, 64), 256>>>(x, Wk, gk, 256, nullptr);
    gemm_tf32<<<dim3(2, 64), 256>>>(x, Wv, gv, 256, nullptr);

    attn_tf32<<<dim3(32, 64), 128>>>(gq, gk, gv, gattn);

    gemm_tf32<<<dim3(8, 64), 256>>>(gattn, Wp, out, 1024, bp);
}

// round 6
// speedup vs baseline: 6.5039x; 2.3012x over previous
#include <cuda_runtime.h>

#define TT 2048
#define BATCH 4

// Scratch: fp16 data stored as packed pairs in unsigned (1 uint = 2 halves).
__device__ unsigned g_q[(size_t)BATCH * TT * 512];    // [b,t,1024h] q * 0.125
__device__ unsigned g_k[(size_t)BATCH * TT * 128];    // [b,t,256h]
__device__ unsigned g_v[(size_t)BATCH * TT * 128];
__device__ unsigned g_attn[(size_t)BATCH * TT * 512];

__device__ __forceinline__ unsigned sptr(const void* p) {
    return (unsigned)__cvta_generic_to_shared(p);
}

__device__ __forceinline__ unsigned pack_h2(float lo, float hi) {
    unsigned r;
    asm("cvt.rn.f16x2.f32 %0, %1, %2;" : "=r"(r) : "f"(hi), "f"(lo));
    return r;
}

__device__ __forceinline__ uint4 pack8(float4 a, float4 b) {
    uint4 u;
    u.x = pack_h2(a.x, a.y);
    u.y = pack_h2(a.z, a.w);
    u.z = pack_h2(b.x, b.y);
    u.w = pack_h2(b.z, b.w);
    return u;
}

__device__ __forceinline__ void ldsm4(unsigned& r0, unsigned& r1, unsigned& r2, unsigned& r3, unsigned a) {
    asm volatile("ldmatrix.sync.aligned.m8n8.x4.shared.b16 {%0,%1,%2,%3},[%4];"
                 : "=r"(r0), "=r"(r1), "=r"(r2), "=r"(r3) : "r"(a));
}

__device__ __forceinline__ void ldsm4t(unsigned& r0, unsigned& r1, unsigned& r2, unsigned& r3, unsigned a) {
    asm volatile("ldmatrix.sync.aligned.m8n8.x4.trans.shared.b16 {%0,%1,%2,%3},[%4];"
                 : "=r"(r0), "=r"(r1), "=r"(r2), "=r"(r3) : "r"(a));
}

__device__ __forceinline__ void mma16(float* d,
                                      unsigned a0, unsigned a1, unsigned a2, unsigned a3,
                                      unsigned b0, unsigned b1) {
    asm volatile("mma.sync.aligned.m16n8k16.row.col.f32.f16.f16.f32 "
                 "{%0,%1,%2,%3},{%4,%5,%6,%7},{%8,%9},{%0,%1,%2,%3};"
                 : "+f"(d[0]), "+f"(d[1]), "+f"(d[2]), "+f"(d[3])
                 : "r"(a0), "r"(a1), "r"(a2), "r"(a3), "r"(b0), "r"(b1));
}

// ---------------------------------------------------------------------------
// GEMM 1: A fp32 [M,1024] @ Bw fp32 [Nh,1024]^T -> C fp16 [M,Nh] * cscale.
// Block 128x128(half cols), BK=64, 256 threads, warp tile 64x32, ldmatrix.
// Shared rows: 32 uints (64 halves, 128B), XOR-8 swizzle on 16B groups.
// ---------------------------------------------------------------------------
__global__ __launch_bounds__(256) void gemm_f2h(
    const float* __restrict__ Ap, const float* __restrict__ Bw,
    unsigned* __restrict__ Cp, int Nu, float cscale)
{
    __shared__ unsigned As[128 * 32];
    __shared__ unsigned Bs[128 * 32];
    const unsigned sA = sptr(As);
    const unsigned sB = sptr(Bs);

    const int tid = threadIdx.x;
    const int lane = tid % 32;
    const int warp = tid / 32;
    const int gid = lane / 4;
    const int tig = lane % 4;
    const int wm = warp / 4;
    const int wn = warp % 4;
    const int m0 = blockIdx.y * 128;
    const int n0 = blockIdx.x * 128;
    const int tr = tid / 4;
    const int tg = (tid % 4) * 2;

    const int arow = wm * 64 + (lane % 16);
    const int ga_add = lane / 16;
    const int brow = wn * 32 + ((lane / 16) % 2) * 8 + (lane % 8);
    const int gb_add = (lane / 8) % 2;

    float acc[4][4][4];
    for (int i = 0; i < 4; i++) {
        for (int j = 0; j < 4; j++) {
            for (int q = 0; q < 4; q++) {
                acc[i][j][q] = 0.f;
            }
        }
    }

    for (int k0 = 0; k0 < 1024; k0 += 64) {
        __syncthreads();
        for (int i = 0; i < 2; i++) {
            int row = tr + i * 64;
            int rx = row % 8;
            for (int j = 0; j < 2; j++) {
                int grp = tg + j;
                const float* asrc = Ap + (m0 + row) * 1024 + k0 + grp * 8;
                float4 fa0 = *(const float4*)(asrc);
                float4 fa1 = *(const float4*)(asrc + 4);
                *(uint4*)(As + row * 32 + (grp ^ rx) * 4) = pack8(fa0, fa1);
                const float* bsrc = Bw + (n0 + row) * 1024 + k0 + grp * 8;
                float4 fb0 = *(const float4*)(bsrc);
                float4 fb1 = *(const float4*)(bsrc + 4);
                *(uint4*)(Bs + row * 32 + (grp ^ rx) * 4) = pack8(fb0, fb1);
            }
        }
        __syncthreads();

        for (int ks = 0; ks < 4; ks++) {
            unsigned af[4][4];
            unsigned bf[2][4];
            for (int mt = 0; mt < 4; mt++) {
                int r = arow + mt * 16;
                int grp = (ks * 2 + ga_add) ^ (r % 8);
                ldsm4(af[mt][0], af[mt][1], af[mt][2], af[mt][3], sA + r * 128 + grp * 16);
            }
            for (int p = 0; p < 2; p++) {
                int r = brow + p * 16;
                int grp = (ks * 2 + gb_add) ^ (r % 8);
                ldsm4(bf[p][0], bf[p][1], bf[p][2], bf[p][3], sB + r * 128 + grp * 16);
            }
            for (int mt = 0; mt < 4; mt++) {
                for (int p = 0; p < 2; p++) {
                    mma16(acc[mt][2 * p + 0], af[mt][0], af[mt][1], af[mt][2], af[mt][3],
                          bf[p][0], bf[p][1]);
                    mma16(acc[mt][2 * p + 1], af[mt][0], af[mt][1], af[mt][2], af[mt][3],
                          bf[p][2], bf[p][3]);
                }
            }
        }
    }

    for (int mt = 0; mt < 4; mt++) {
        for (int nt = 0; nt < 4; nt++) {
            int row = m0 + wm * 64 + mt * 16 + gid;
            int colu = (n0 + wn * 32 + nt * 8 + 2 * tig) / 2;
            Cp[row * Nu + colu] = pack_h2(acc[mt][nt][0] * cscale, acc[mt][nt][1] * cscale);
            Cp[(row + 8) * Nu + colu] = pack_h2(acc[mt][nt][2] * cscale, acc[mt][nt][3] * cscale);
        }
    }
}

// ---------------------------------------------------------------------------
// GEMM 2: A fp16 [M,1024] @ Bw fp32 [1024,1024]^T -> C fp32 + bias.
// ---------------------------------------------------------------------------
__global__ __launch_bounds__(256) void gemm_h2f(
    const unsigned* __restrict__ Ap, const float* __restrict__ Bw,
    float* __restrict__ Cp, const float* __restrict__ bias)
{
    __shared__ unsigned As[128 * 32];
    __shared__ unsigned Bs[128 * 32];
    const unsigned sA = sptr(As);
    const unsigned sB = sptr(Bs);

    const int tid = threadIdx.x;
    const int lane = tid % 32;
    const int warp = tid / 32;
    const int gid = lane / 4;
    const int tig = lane % 4;
    const int wm = warp / 4;
    const int wn = warp % 4;
    const int m0 = blockIdx.y * 128;
    const int n0 = blockIdx.x * 128;
    const int tr = tid / 4;
    const int tg = (tid % 4) * 2;

    const int arow = wm * 64 + (lane % 16);
    const int ga_add = lane / 16;
    const int brow = wn * 32 + ((lane / 16) % 2) * 8 + (lane % 8);
    const int gb_add = (lane / 8) % 2;

    float acc[4][4][4];
    for (int i = 0; i < 4; i++) {
        for (int j = 0; j < 4; j++) {
            for (int q = 0; q < 4; q++) {
                acc[i][j][q] = 0.f;
            }
        }
    }

    for (int k0 = 0; k0 < 1024; k0 += 64) {
        int k0u = k0 / 2;
        __syncthreads();
        for (int i = 0; i < 2; i++) {
            int row = tr + i * 64;
            int rx = row % 8;
            for (int j = 0; j < 2; j++) {
                int grp = tg + j;
                uint4 va = *(const uint4*)(Ap + (m0 + row) * 512 + k0u + grp * 4);
                *(uint4*)(As + row * 32 + (grp ^ rx) * 4) = va;
                const float* bsrc = Bw + (n0 + row) * 1024 + k0 + grp * 8;
                float4 fb0 = *(const float4*)(bsrc);
                float4 fb1 = *(const float4*)(bsrc + 4);
                *(uint4*)(Bs + row * 32 + (grp ^ rx) * 4) = pack8(fb0, fb1);
            }
        }
        __syncthreads();

        for (int ks = 0; ks < 4; ks++) {
            unsigned af[4][4];
            unsigned bf[2][4];
            for (int mt = 0; mt < 4; mt++) {
                int r = arow + mt * 16;
                int grp = (ks * 2 + ga_add) ^ (r % 8);
                ldsm4(af[mt][0], af[mt][1], af[mt][2], af[mt][3], sA + r * 128 + grp * 16);
            }
            for (int p = 0; p < 2; p++) {
                int r = brow + p * 16;
                int grp = (ks * 2 + gb_add) ^ (r % 8);
                ldsm4(bf[p][0], bf[p][1], bf[p][2], bf[p][3], sB + r * 128 + grp * 16);
            }
            for (int mt = 0; mt < 4; mt++) {
                for (int p = 0; p < 2; p++) {
                    mma16(acc[mt][2 * p + 0], af[mt][0], af[mt][1], af[mt][2], af[mt][3],
                          bf[p][0], bf[p][1]);
                    mma16(acc[mt][2 * p + 1], af[mt][0], af[mt][1], af[mt][2], af[mt][3],
                          bf[p][2], bf[p][3]);
                }
            }
        }
    }

    for (int mt = 0; mt < 4; mt++) {
        for (int nt = 0; nt < 4; nt++) {
            int row = m0 + wm * 64 + mt * 16 + gid;
            int col = n0 + wn * 32 + nt * 8 + 2 * tig;
            float bb0 = bias[col];
            float bb1 = bias[col + 1];
            *(float2*)(Cp + row * 1024 + col) =
                make_float2(acc[mt][nt][0] + bb0, acc[mt][nt][1] + bb1);
            *(float2*)(Cp + (row + 8) * 1024 + col) =
                make_float2(acc[mt][nt][2] + bb0, acc[mt][nt][3] + bb1);
        }
    }
}

// ---------------------------------------------------------------------------
// Flash attention, fp16 mma, 4 warps per 64-query tile. P stays in registers.
// ---------------------------------------------------------------------------
__device__ __forceinline__ void stage64u(unsigned* dst, const unsigned* src, int gsu, int tid) {
    int r = tid / 2;
    const unsigned* srow = src + r * gsu;
    unsigned* drow = dst + r * 32;
    int rx = r % 8;
    for (int j = 0; j < 4; j++) {
        int grp = j * 2 + (tid % 2);
        *(uint4*)(drow + (grp ^ rx) * 4) = *(const uint4*)(srow + grp * 4);
    }
}

__global__ __launch_bounds__(128) void attn_h(
    const unsigned* __restrict__ qbuf, const unsigned* __restrict__ kbuf,
    const unsigned* __restrict__ vbuf, unsigned* __restrict__ obuf)
{
    __shared__ unsigned Qs[64 * 32];
    __shared__ unsigned Ks[64 * 32];
    __shared__ unsigned Vs[64 * 32];
    const unsigned sQ = sptr(Qs);
    const unsigned sK = sptr(Ks);
    const unsigned sV = sptr(Vs);

    const int tid = threadIdx.x;
    const int lane = tid % 32;
    const int warp = tid / 32;
    const int gid = lane / 4;
    const int tig = lane % 4;
    const int q0 = blockIdx.x * 64;
    const int bh = blockIdx.y;
    const int bb = bh / 16;
    const int hh = bh % 16;
    const int gg = hh / 4;

    stage64u(Qs, qbuf + (bb * TT + q0) * 512 + hh * 32, 512, tid);
    __syncthreads();

    unsigned qf[4][4];
    const int qrow = warp * 16 + (lane % 16);
    const int qga = lane / 16;
    for (int ks = 0; ks < 4; ks++) {
        int grp = (ks * 2 + qga) ^ (qrow % 8);
        ldsm4(qf[ks][0], qf[ks][1], qf[ks][2], qf[ks][3], sQ + qrow * 128 + grp * 16);
    }

    float oacc[8][4];
    for (int nt = 0; nt < 8; nt++) {
        for (int q = 0; q < 4; q++) {
            oacc[nt][q] = 0.f;
        }
    }
    float m0r = -1e30f;
    float m1r = -1e30f;
    float l0r = 0.f;
    float l1r = 0.f;

    const int row0 = q0 + 16 * warp + gid;
    const int row1 = row0 + 8;
    const int diag = q0 / 64;

    const unsigned* kb = kbuf + bb * TT * 128 + gg * 32;
    const unsigned* vb = vbuf + bb * TT * 128 + gg * 32;

    const int s_nadd = ((lane / 16) % 2) * 8 + (lane % 8);
    const int s_gadd = (lane / 8) % 2;
    const int v_kadd = ((lane / 8) % 2) * 8 + (lane % 8);
    const int v_gadd = (lane / 16) % 2;

    for (int kt = 0; kt <= diag; kt++) {
        __syncthreads();
        stage64u(Ks, kb + kt * 64 * 128, 128, tid);
        stage64u(Vs, vb + kt * 64 * 128, 128, tid);
        __syncthreads();

        float sc[8][4];
        for (int nt = 0; nt < 8; nt++) {
            for (int q = 0; q < 4; q++) {
                sc[nt][q] = 0.f;
            }
        }
        for (int ks = 0; ks < 4; ks++) {
            for (int p = 0; p < 4; p++) {
                int nrow = p * 16 + s_nadd;
                int grp = (ks * 2 + s_gadd) ^ (nrow % 8);
                unsigned kf0, kf1, kf2, kf3;
                ldsm4(kf0, kf1, kf2, kf3, sK + nrow * 128 + grp * 16);
                mma16(sc[2 * p + 0], qf[ks][0], qf[ks][1], qf[ks][2], qf[ks][3], kf0, kf1);
                mma16(sc[2 * p + 1], qf[ks][0], qf[ks][1], qf[ks][2], qf[ks][3], kf2, kf3);
            }
        }

        if (kt == diag) {
            for (int nt = 0; nt < 8; nt++) {
                int kcol = kt * 64 + nt * 8 + 2 * tig;
                if (kcol > row0) { sc[nt][0] = -1e30f; }
                if (kcol + 1 > row0) { sc[nt][1] = -1e30f; }
                if (kcol > row1) { sc[nt][2] = -1e30f; }
                if (kcol + 1 > row1) { sc[nt][3] = -1e30f; }
            }
        }

        float mt0 = -1e30f;
        float mt1 = -1e30f;
        for (int nt = 0; nt < 8; nt++) {
            mt0 = fmaxf(mt0, fmaxf(sc[nt][0], sc[nt][1]));
            mt1 = fmaxf(mt1, fmaxf(sc[nt][2], sc[nt][3]));
        }
        mt0 = fmaxf(mt0, __shfl_xor_sync(0xffffffffu, mt0, 1));
        mt0 = fmaxf(mt0, __shfl_xor_sync(0xffffffffu, mt0, 2));
        mt1 = fmaxf(mt1, __shfl_xor_sync(0xffffffffu, mt1, 1));
        mt1 = fmaxf(mt1, __shfl_xor_sync(0xffffffffu, mt1, 2));
        float mn0 = fmaxf(m0r, mt0);
        float mn1 = fmaxf(m1r, mt1);
        float c0 = __expf(m0r - mn0);
        float c1 = __expf(m1r - mn1);
        float ps0 = 0.f;
        float ps1 = 0.f;
        for (int nt = 0; nt < 8; nt++) {
            sc[nt][0] = __expf(sc[nt][0] - mn0);
            sc[nt][1] = __expf(sc[nt][1] - mn0);
            sc[nt][2] = __expf(sc[nt][2] - mn1);
            sc[nt][3] = __expf(sc[nt][3] - mn1);
            ps0 += sc[nt][0] + sc[nt][1];
            ps1 += sc[nt][2] + sc[nt][3];
            oacc[nt][0] *= c0;
            oacc[nt][1] *= c0;
            oacc[nt][2] *= c1;
            oacc[nt][3] *= c1;
        }
        ps0 += __shfl_xor_sync(0xffffffffu, ps0, 1);
        ps0 += __shfl_xor_sync(0xffffffffu, ps0, 2);
        ps1 += __shfl_xor_sync(0xffffffffu, ps1, 1);
        ps1 += __shfl_xor_sync(0xffffffffu, ps1, 2);
        l0r = l0r * c0 + ps0;
        l1r = l1r * c1 + ps1;
        m0r = mn0;
        m1r = mn1;

        for (int ks = 0; ks < 4; ks++) {
            unsigned pf0 = pack_h2(sc[2 * ks + 0][0], sc[2 * ks + 0][1]);
            unsigned pf1 = pack_h2(sc[2 * ks + 0][2], sc[2 * ks + 0][3]);
            unsigned pf2 = pack_h2(sc[2 * ks + 1][0], sc[2 * ks + 1][1]);
            unsigned pf3 = pack_h2(sc[2 * ks + 1][2], sc[2 * ks + 1][3]);
            for (int p = 0; p < 4; p++) {
                int krow = ks * 16 + v_kadd;
                int grp = (p * 2 + v_gadd) ^ (krow % 8);
                unsigned vf0, vf1, vf2, vf3;
                ldsm4t(vf0, vf1, vf2, vf3, sV + krow * 128 + grp * 16);
                mma16(oacc[2 * p + 0], pf0, pf1, pf2, pf3, vf0, vf1);
                mma16(oacc[2 * p + 1], pf0, pf1, pf2, pf3, vf2, vf3);
            }
        }
    }

    const float i0 = 1.f / l0r;
    const float i1 = 1.f / l1r;
    for (int nt = 0; nt < 8; nt++) {
        int colu = (hh * 64 + nt * 8 + 2 * tig) / 2;
        obuf[(bb * TT + row0) * 512 + colu] = pack_h2(oacc[nt][0] * i0, oacc[nt][1] * i0);
        obuf[(bb * TT + row1) * 512 + colu] = pack_h2(oacc[nt][2] * i1, oacc[nt][3] * i1);
    }
}

extern "C" void kernel_launch(void* const* d_in, const int* in_sizes, int n_in,
                              void* d_out, int out_size)
{
    const float* x  = (const float*)d_in[0];
    const float* Wq = (const float*)d_in[1];
    const float* Wk = (const float*)d_in[2];
    const float* Wv = (const float*)d_in[3];
    const float* Wp = (const float*)d_in[4];
    const float* bp = (const float*)d_in[5];
    float* out = (float*)d_out;

    unsigned* gq = 0;
    unsigned* gk = 0;
    unsigned* gv = 0;
    unsigned* ga = 0;
    cudaGetSymbolAddress((void**)&gq, g_q);
    cudaGetSymbolAddress((void**)&gk, g_k);
    cudaGetSymbolAddress((void**)&gv, g_v);
    cudaGetSymbolAddress((void**)&ga, g_attn);

    gemm_f2h<<<dim3(8, 64), 256>>>(x, Wq, gq, 512, 0.125f);
    gemm_f2h<<<dim3(2, 64), 256>>>(x, Wk, gk, 128, 1.f);
    gemm_f2h<<<dim3(2, 64), 256>>>(x, Wv, gv, 128, 1.f);

    attn_h<<<dim3(32, 64), 128>>>(gq, gk, gv, ga);

    gemm_h2f<<<dim3(8, 64), 256>>>(ga, Wp, out, bp);
}

// round 7
// speedup vs baseline: 8.6263x; 1.3263x over previous
#include <cuda_runtime.h>

#define TT 2048
#define BATCH 4

// fp16 packed-pair scratch (1 unsigned = 2 halves). Allocation is forbidden.
__device__ unsigned g_x[(size_t)BATCH * TT * 512];    // x fp16 [b,t,1024h]
__device__ unsigned g_wq[512 * 1024];                 // Wq*0.125 fp16 [1024,1024h]
__device__ unsigned g_wk[512 * 256];                  // Wk fp16 [256,1024h]
__device__ unsigned g_wv[512 * 256];
__device__ unsigned g_wp[512 * 1024];                 // Wp fp16 [1024,1024h]
__device__ unsigned g_q[(size_t)BATCH * TT * 512];    // q fp16 (pre-scaled)
__device__ unsigned g_k[(size_t)BATCH * TT * 128];
__device__ unsigned g_v[(size_t)BATCH * TT * 128];
__device__ unsigned g_attn[(size_t)BATCH * TT * 512];

__device__ __forceinline__ unsigned sptr(const void* p) {
    return (unsigned)__cvta_generic_to_shared(p);
}

__device__ __forceinline__ unsigned pack_h2(float lo, float hi) {
    unsigned r;
    asm("cvt.rn.f16x2.f32 %0, %1, %2;" : "=r"(r) : "f"(hi), "f"(lo));
    return r;
}

__device__ __forceinline__ void ldsm4(unsigned& r0, unsigned& r1, unsigned& r2, unsigned& r3, unsigned a) {
    asm volatile("ldmatrix.sync.aligned.m8n8.x4.shared.b16 {%0,%1,%2,%3},[%4];"
                 : "=r"(r0), "=r"(r1), "=r"(r2), "=r"(r3) : "r"(a));
}

__device__ __forceinline__ void ldsm4t(unsigned& r0, unsigned& r1, unsigned& r2, unsigned& r3, unsigned a) {
    asm volatile("ldmatrix.sync.aligned.m8n8.x4.trans.shared.b16 {%0,%1,%2,%3},[%4];"
                 : "=r"(r0), "=r"(r1), "=r"(r2), "=r"(r3) : "r"(a));
}

__device__ __forceinline__ void mma16(float* d,
                                      unsigned a0, unsigned a1, unsigned a2, unsigned a3,
                                      unsigned b0, unsigned b1) {
    asm volatile("mma.sync.aligned.m16n8k16.row.col.f32.f16.f16.f32 "
                 "{%0,%1,%2,%3},{%4,%5,%6,%7},{%8,%9},{%0,%1,%2,%3};"
                 : "+f"(d[0]), "+f"(d[1]), "+f"(d[2]), "+f"(d[3])
                 : "r"(a0), "r"(a1), "r"(a2), "r"(a3), "r"(b0), "r"(b1));
}

// ---------------------------------------------------------------------------
// fp32 -> fp16 pair conversion (with scale), vectorized by 4 floats.
// ---------------------------------------------------------------------------
__global__ __launch_bounds__(256) void conv_f2h(
    const float* __restrict__ in, unsigned* __restrict__ out, int n4, float scale)
{
    int i = blockIdx.x * 256 + threadIdx.x;
    if (i < n4) {
        float4 f = ((const float4*)in)[i];
        uint2 u;
        u.x = pack_h2(f.x * scale, f.y * scale);
        u.y = pack_h2(f.z * scale, f.w * scale);
        ((uint2*)out)[i] = u;
    }
}

// ---------------------------------------------------------------------------
// GEMM (all fp16 in): C[M,2*Nu h] = A[M,1024] @ B[N,1024]^T, fp16 out.
// Block 128x128, BK=64, 256 threads, warp tile 64x32, ldmatrix + XOR swizzle.
// ---------------------------------------------------------------------------
__global__ __launch_bounds__(256) void gemm_hh_h(
    const unsigned* __restrict__ Ap, const unsigned* __restrict__ Bp,
    unsigned* __restrict__ Cp, int Nu)
{
    __shared__ unsigned As[128 * 32];
    __shared__ unsigned Bs[128 * 32];
    const unsigned sA = sptr(As);
    const unsigned sB = sptr(Bs);

    const int tid = threadIdx.x;
    const int lane = tid % 32;
    const int warp = tid / 32;
    const int gid = lane / 4;
    const int tig = lane % 4;
    const int wm = warp / 4;
    const int wn = warp % 4;
    const int m0 = blockIdx.y * 128;
    const int n0 = blockIdx.x * 128;
    const int tr = tid / 4;
    const int tg = (tid % 4) * 2;

    const int arow = wm * 64 + (lane % 16);
    const int ga_add = lane / 16;
    const int brow = wn * 32 + ((lane / 16) % 2) * 8 + (lane % 8);
    const int gb_add = (lane / 8) % 2;

    float acc[4][4][4];
    for (int i = 0; i < 4; i++) {
        for (int j = 0; j < 4; j++) {
            for (int q = 0; q < 4; q++) {
                acc[i][j][q] = 0.f;
            }
        }
    }

    for (int k0u = 0; k0u < 512; k0u += 32) {
        __syncthreads();
        for (int i = 0; i < 2; i++) {
            int row = tr + i * 64;
            int rx = row % 8;
            for (int j = 0; j < 2; j++) {
                int grp = tg + j;
                uint4 va = *(const uint4*)(Ap + (m0 + row) * 512 + k0u + grp * 4);
                *(uint4*)(As + row * 32 + (grp ^ rx) * 4) = va;
                uint4 vb = *(const uint4*)(Bp + (n0 + row) * 512 + k0u + grp * 4);
                *(uint4*)(Bs + row * 32 + (grp ^ rx) * 4) = vb;
            }
        }
        __syncthreads();

        for (int ks = 0; ks < 4; ks++) {
            unsigned af[4][4];
            unsigned bf[2][4];
            for (int mt = 0; mt < 4; mt++) {
                int r = arow + mt * 16;
                int grp = (ks * 2 + ga_add) ^ (r % 8);
                ldsm4(af[mt][0], af[mt][1], af[mt][2], af[mt][3], sA + r * 128 + grp * 16);
            }
            for (int p = 0; p < 2; p++) {
                int r = brow + p * 16;
                int grp = (ks * 2 + gb_add) ^ (r % 8);
                ldsm4(bf[p][0], bf[p][1], bf[p][2], bf[p][3], sB + r * 128 + grp * 16);
            }
            for (int mt = 0; mt < 4; mt++) {
                for (int p = 0; p < 2; p++) {
                    mma16(acc[mt][2 * p + 0], af[mt][0], af[mt][1], af[mt][2], af[mt][3],
                          bf[p][0], bf[p][1]);
                    mma16(acc[mt][2 * p + 1], af[mt][0], af[mt][1], af[mt][2], af[mt][3],
                          bf[p][2], bf[p][3]);
                }
            }
        }
    }

    for (int mt = 0; mt < 4; mt++) {
        for (int nt = 0; nt < 4; nt++) {
            int row = m0 + wm * 64 + mt * 16 + gid;
            int colu = (n0 + wn * 32 + nt * 8 + 2 * tig) / 2;
            Cp[row * Nu + colu] = pack_h2(acc[mt][nt][0], acc[mt][nt][1]);
            Cp[(row + 8) * Nu + colu] = pack_h2(acc[mt][nt][2], acc[mt][nt][3]);
        }
    }
}

// ---------------------------------------------------------------------------
// GEMM (fp16 in): C fp32 [M,1024] = A @ B^T + bias.
// ---------------------------------------------------------------------------
__global__ __launch_bounds__(256) void gemm_hh_f(
    const unsigned* __restrict__ Ap, const unsigned* __restrict__ Bp,
    float* __restrict__ Cp, const float* __restrict__ bias)
{
    __shared__ unsigned As[128 * 32];
    __shared__ unsigned Bs[128 * 32];
    const unsigned sA = sptr(As);
    const unsigned sB = sptr(Bs);

    const int tid = threadIdx.x;
    const int lane = tid % 32;
    const int warp = tid / 32;
    const int gid = lane / 4;
    const int tig = lane % 4;
    const int wm = warp / 4;
    const int wn = warp % 4;
    const int m0 = blockIdx.y * 128;
    const int n0 = blockIdx.x * 128;
    const int tr = tid / 4;
    const int tg = (tid % 4) * 2;

    const int arow = wm * 64 + (lane % 16);
    const int ga_add = lane / 16;
    const int brow = wn * 32 + ((lane / 16) % 2) * 8 + (lane % 8);
    const int gb_add = (lane / 8) % 2;

    float acc[4][4][4];
    for (int i = 0; i < 4; i++) {
        for (int j = 0; j < 4; j++) {
            for (int q = 0; q < 4; q++) {
                acc[i][j][q] = 0.f;
            }
        }
    }

    for (int k0u = 0; k0u < 512; k0u += 32) {
        __syncthreads();
        for (int i = 0; i < 2; i++) {
            int row = tr + i * 64;
            int rx = row % 8;
            for (int j = 0; j < 2; j++) {
                int grp = tg + j;
                uint4 va = *(const uint4*)(Ap + (m0 + row) * 512 + k0u + grp * 4);
                *(uint4*)(As + row * 32 + (grp ^ rx) * 4) = va;
                uint4 vb = *(const uint4*)(Bp + (n0 + row) * 512 + k0u + grp * 4);
                *(uint4*)(Bs + row * 32 + (grp ^ rx) * 4) = vb;
            }
        }
        __syncthreads();

        for (int ks = 0; ks < 4; ks++) {
            unsigned af[4][4];
            unsigned bf[2][4];
            for (int mt = 0; mt < 4; mt++) {
                int r = arow + mt * 16;
                int grp = (ks * 2 + ga_add) ^ (r % 8);
                ldsm4(af[mt][0], af[mt][1], af[mt][2], af[mt][3], sA + r * 128 + grp * 16);
            }
            for (int p = 0; p < 2; p++) {
                int r = brow + p * 16;
                int grp = (ks * 2 + gb_add) ^ (r % 8);
                ldsm4(bf[p][0], bf[p][1], bf[p][2], bf[p][3], sB + r * 128 + grp * 16);
            }
            for (int mt = 0; mt < 4; mt++) {
                for (int p = 0; p < 2; p++) {
                    mma16(acc[mt][2 * p + 0], af[mt][0], af[mt][1], af[mt][2], af[mt][3],
                          bf[p][0], bf[p][1]);
                    mma16(acc[mt][2 * p + 1], af[mt][0], af[mt][1], af[mt][2], af[mt][3],
                          bf[p][2], bf[p][3]);
                }
            }
        }
    }

    for (int mt = 0; mt < 4; mt++) {
        for (int nt = 0; nt < 4; nt++) {
            int row = m0 + wm * 64 + mt * 16 + gid;
            int col = n0 + wn * 32 + nt * 8 + 2 * tig;
            float bb0 = bias[col];
            float bb1 = bias[col + 1];
            *(float2*)(Cp + row * 1024 + col) =
                make_float2(acc[mt][nt][0] + bb0, acc[mt][nt][1] + bb1);
            *(float2*)(Cp + (row + 8) * 1024 + col) =
                make_float2(acc[mt][nt][2] + bb0, acc[mt][nt][3] + bb1);
        }
    }
}

// ---------------------------------------------------------------------------
// Flash attention: Br=128, 4 warps, 32 query rows per warp (2 m-tiles).
// Each K/V fragment load feeds 4 MMAs. P stays in registers.
// ---------------------------------------------------------------------------
__global__ __launch_bounds__(128) void attn_h(
    const unsigned* __restrict__ qbuf, const unsigned* __restrict__ kbuf,
    const unsigned* __restrict__ vbuf, unsigned* __restrict__ obuf)
{
    __shared__ unsigned Qs[128 * 32];
    __shared__ unsigned Ks[64 * 32];
    __shared__ unsigned Vs[64 * 32];
    const unsigned sQ = sptr(Qs);
    const unsigned sK = sptr(Ks);
    const unsigned sV = sptr(Vs);

    const int tid = threadIdx.x;
    const int lane = tid % 32;
    const int warp = tid / 32;
    const int gid = lane / 4;
    const int tig = lane % 4;
    const int q0 = blockIdx.x * 128;
    const int bh = blockIdx.y;
    const int bb = bh / 16;
    const int hh = bh % 16;
    const int gg = hh / 4;

    // Stage Q: 128 rows, one row per thread, 8 x 16B groups.
    {
        const unsigned* srow = qbuf + (bb * TT + q0 + tid) * 512 + hh * 32;
        unsigned* drow = Qs + tid * 32;
        int rx = tid % 8;
        for (int grp = 0; grp < 8; grp++) {
            *(uint4*)(drow + (grp ^ rx) * 4) = *(const uint4*)(srow + grp * 4);
        }
    }
    __syncthreads();

    // Q fragments: 2 m-tiles x 4 k-steps.
    unsigned qf[2][4][4];
    const int qga = lane / 16;
    for (int mt = 0; mt < 2; mt++) {
        int qrow = warp * 32 + mt * 16 + (lane % 16);
        for (int ks = 0; ks < 4; ks++) {
            int grp = (ks * 2 + qga) ^ (qrow % 8);
            ldsm4(qf[mt][ks][0], qf[mt][ks][1], qf[mt][ks][2], qf[mt][ks][3],
                  sQ + qrow * 128 + grp * 16);
        }
    }

    float oacc[2][8][4];
    for (int mt = 0; mt < 2; mt++) {
        for (int nt = 0; nt < 8; nt++) {
            for (int q = 0; q < 4; q++) {
                oacc[mt][nt][q] = 0.f;
            }
        }
    }
    float mr[2][2];
    float lr[2][2];
    for (int mt = 0; mt < 2; mt++) {
        mr[mt][0] = -1e30f; mr[mt][1] = -1e30f;
        lr[mt][0] = 0.f; lr[mt][1] = 0.f;
    }

    const int rw0 = q0 + warp * 32;          // first row of this warp
    const int kmax = q0 / 64 + 1;

    const unsigned* kb = kbuf + bb * TT * 128 + gg * 32;
    const unsigned* vb = vbuf + bb * TT * 128 + gg * 32;

    const int s_nadd = ((lane / 16) % 2) * 8 + (lane % 8);
    const int s_gadd = (lane / 8) % 2;
    const int v_kadd = ((lane / 8) % 2) * 8 + (lane % 8);
    const int v_gadd = (lane / 16) % 2;

    for (int kt = 0; kt <= kmax; kt++) {
        __syncthreads();
        // Stage K and V: 64 rows each, 2 threads per row, 4 groups per thread.
        {
            int r = tid / 2;
            int rx = r % 8;
            const unsigned* ksrc = kb + (kt * 64 + r) * 128;
            const unsigned* vsrc = vb + (kt * 64 + r) * 128;
            unsigned* kdst = Ks + r * 32;
            unsigned* vdst = Vs + r * 32;
            for (int j = 0; j < 4; j++) {
                int grp = j * 2 + (tid % 2);
                *(uint4*)(kdst + (grp ^ rx) * 4) = *(const uint4*)(ksrc + grp * 4);
                *(uint4*)(vdst + (grp ^ rx) * 4) = *(const uint4*)(vsrc + grp * 4);
            }
        }
        __syncthreads();

        if (kt * 64 > rw0 + 31) { continue; }   // warp fully masked for this tile

        float sc[2][8][4];
        for (int mt = 0; mt < 2; mt++) {
            for (int nt = 0; nt < 8; nt++) {
                for (int q = 0; q < 4; q++) {
                    sc[mt][nt][q] = 0.f;
                }
            }
        }
        for (int ks = 0; ks < 4; ks++) {
            for (int p = 0; p < 4; p++) {
                int nrow = p * 16 + s_nadd;
                int grp = (ks * 2 + s_gadd) ^ (nrow % 8);
                unsigned kf0, kf1, kf2, kf3;
                ldsm4(kf0, kf1, kf2, kf3, sK + nrow * 128 + grp * 16);
                for (int mt = 0; mt < 2; mt++) {
                    mma16(sc[mt][2 * p + 0], qf[mt][ks][0], qf[mt][ks][1], qf[mt][ks][2], qf[mt][ks][3], kf0, kf1);
                    mma16(sc[mt][2 * p + 1], qf[mt][ks][0], qf[mt][ks][1], qf[mt][ks][2], qf[mt][ks][3], kf2, kf3);
                }
            }
        }

        if (kt * 64 + 63 > rw0) {   // tile may be partially masked
            for (int mt = 0; mt < 2; mt++) {
                int rowA = rw0 + mt * 16 + gid;
                int rowB = rowA + 8;
                for (int nt = 0; nt < 8; nt++) {
                    int kcol = kt * 64 + nt * 8 + 2 * tig;
                    if (kcol > rowA) { sc[mt][nt][0] = -1e30f; }
                    if (kcol + 1 > rowA) { sc[mt][nt][1] = -1e30f; }
                    if (kcol > rowB) { sc[mt][nt][2] = -1e30f; }
                    if (kcol + 1 > rowB) { sc[mt][nt][3] = -1e30f; }
                }
            }
        }

        for (int mt = 0; mt < 2; mt++) {
            float mt0 = -1e30f;
            float mt1 = -1e30f;
            for (int nt = 0; nt < 8; nt++) {
                mt0 = fmaxf(mt0, fmaxf(sc[mt][nt][0], sc[mt][nt][1]));
                mt1 = fmaxf(mt1, fmaxf(sc[mt][nt][2], sc[mt][nt][3]));
            }
            mt0 = fmaxf(mt0, __shfl_xor_sync(0xffffffffu, mt0, 1));
            mt0 = fmaxf(mt0, __shfl_xor_sync(0xffffffffu, mt0, 2));
            mt1 = fmaxf(mt1, __shfl_xor_sync(0xffffffffu, mt1, 1));
            mt1 = fmaxf(mt1, __shfl_xor_sync(0xffffffffu, mt1, 2));
            float mn0 = fmaxf(mr[mt][0], mt0);
            float mn1 = fmaxf(mr[mt][1], mt1);
            float c0 = __expf(mr[mt][0] - mn0);
            float c1 = __expf(mr[mt][1] - mn1);
            float ps0 = 0.f;
            float ps1 = 0.f;
            for (int nt = 0; nt < 8; nt++) {
                sc[mt][nt][0] = __expf(sc[mt][nt][0] - mn0);
                sc[mt][nt][1] = __expf(sc[mt][nt][1] - mn0);
                sc[mt][nt][2] = __expf(sc[mt][nt][2] - mn1);
                sc[mt][nt][3] = __expf(sc[mt][nt][3] - mn1);
                ps0 += sc[mt][nt][0] + sc[mt][nt][1];
                ps1 += sc[mt][nt][2] + sc[mt][nt][3];
                oacc[mt][nt][0] *= c0;
                oacc[mt][nt][1] *= c0;
                oacc[mt][nt][2] *= c1;
                oacc[mt][nt][3] *= c1;
            }
            ps0 += __shfl_xor_sync(0xffffffffu, ps0, 1);
            ps0 += __shfl_xor_sync(0xffffffffu, ps0, 2);
            ps1 += __shfl_xor_sync(0xffffffffu, ps1, 1);
            ps1 += __shfl_xor_sync(0xffffffffu, ps1, 2);
            lr[mt][0] = lr[mt][0] * c0 + ps0;
            lr[mt][1] = lr[mt][1] * c1 + ps1;
            mr[mt][0] = mn0;
            mr[mt][1] = mn1;
        }

        for (int ks = 0; ks < 4; ks++) {
            unsigned pf[2][4];
            for (int mt = 0; mt < 2; mt++) {
                pf[mt][0] = pack_h2(sc[mt][2 * ks + 0][0], sc[mt][2 * ks + 0][1]);
                pf[mt][1] = pack_h2(sc[mt][2 * ks + 0][2], sc[mt][2 * ks + 0][3]);
                pf[mt][2] = pack_h2(sc[mt][2 * ks + 1][0], sc[mt][2 * ks + 1][1]);
                pf[mt][3] = pack_h2(sc[mt][2 * ks + 1][2], sc[mt][2 * ks + 1][3]);
            }
            for (int p = 0; p < 4; p++) {
                int krow = ks * 16 + v_kadd;
                int grp = (p * 2 + v_gadd) ^ (krow % 8);
                unsigned vf0, vf1, vf2, vf3;
                ldsm4t(vf0, vf1, vf2, vf3, sV + krow * 128 + grp * 16);
                for (int mt = 0; mt < 2; mt++) {
                    mma16(oacc[mt][2 * p + 0], pf[mt][0], pf[mt][1], pf[mt][2], pf[mt][3], vf0, vf1);
                    mma16(oacc[mt][2 * p + 1], pf[mt][0], pf[mt][1], pf[mt][2], pf[mt][3], vf2, vf3);
                }
            }
        }
    }

    for (int mt = 0; mt < 2; mt++) {
        float i0 = 1.f / lr[mt][0];
        float i1 = 1.f / lr[mt][1];
        int rowA = rw0 + mt * 16 + gid;
        int rowB = rowA + 8;
        for (int nt = 0; nt < 8; nt++) {
            int colu = hh * 32 + nt * 4 + tig;
            obuf[(bb * TT + rowA) * 512 + colu] = pack_h2(oacc[mt][nt][0] * i0, oacc[mt][nt][1] * i0);
            obuf[(bb * TT + rowB) * 512 + colu] = pack_h2(oacc[mt][nt][2] * i1, oacc[mt][nt][3] * i1);
        }
    }
}

extern "C" void kernel_launch(void* const* d_in, const int* in_sizes, int n_in,
                              void* d_out, int out_size)
{
    const float* x  = (const float*)d_in[0];
    const float* Wq = (const float*)d_in[1];
    const float* Wk = (const float*)d_in[2];
    const float* Wv = (const float*)d_in[3];
    const float* Wp = (const float*)d_in[4];
    const float* bp = (const float*)d_in[5];
    float* out = (float*)d_out;

    unsigned* gx = 0;
    unsigned* gwq = 0;
    unsigned* gwk = 0;
    unsigned* gwv = 0;
    unsigned* gwp = 0;
    unsigned* gq = 0;
    unsigned* gk = 0;
    unsigned* gv = 0;
    unsigned* ga = 0;
    cudaGetSymbolAddress((void**)&gx, g_x);
    cudaGetSymbolAddress((void**)&gwq, g_wq);
    cudaGetSymbolAddress((void**)&gwk, g_wk);
    cudaGetSymbolAddress((void**)&gwv, g_wv);
    cudaGetSymbolAddress((void**)&gwp, g_wp);
    cudaGetSymbolAddress((void**)&gq, g_q);
    cudaGetSymbolAddress((void**)&gk, g_k);
    cudaGetSymbolAddress((void**)&gv, g_v);
    cudaGetSymbolAddress((void**)&ga, g_attn);

    // Convert inputs to fp16 (softmax scale folded into Wq).
    conv_f2h<<<8192, 256>>>(x, gx, 2097152, 1.f);
    conv_f2h<<<1024, 256>>>(Wq, gwq, 262144, 0.125f);
    conv_f2h<<<256, 256>>>(Wk, gwk, 65536, 1.f);
    conv_f2h<<<256, 256>>>(Wv, gwv, 65536, 1.f);
    conv_f2h<<<1024, 256>>>(Wp, gwp, 262144, 1.f);

    gemm_hh_h<<<dim3(8, 64), 256>>>(gx, gwq, gq, 512);
    gemm_hh_h<<<dim3(2, 64), 256>>>(gx, gwk, gk, 128);
    gemm_hh_h<<<dim3(2, 64), 256>>>(gx, gwv, gv, 128);

    attn_h<<<dim3(16, 64), 128>>>(gq, gk, gv, ga);

    gemm_hh_f<<<dim3(8, 64), 256>>>(ga, gwp, out, bp);
}

// round 8
// speedup vs baseline: 9.6501x; 1.1187x over previous
#include <cuda_runtime.h>

#define TT 2048
#define BATCH 4

// fp16 packed-pair scratch (1 unsigned = 2 halves). Allocation is forbidden.
__device__ unsigned g_x[(size_t)BATCH * TT * 512];     // x fp16 [b,t,1024h]
__device__ unsigned g_wq[512 * 1024];                  // Wq*0.125 fp16
__device__ unsigned g_wkv[512 * 512];                  // [Wk rows 0..255 | Wv rows 256..511]
__device__ unsigned g_wp[512 * 1024];
__device__ unsigned g_q[(size_t)BATCH * TT * 512];     // q fp16 (pre-scaled)
__device__ unsigned g_kv[(size_t)BATCH * TT * 256];    // [b,t, k 128u | v 128u]
__device__ unsigned g_attn[(size_t)BATCH * TT * 512];

__device__ __forceinline__ unsigned sptr(const void* p) {
    return (unsigned)__cvta_generic_to_shared(p);
}

__device__ __forceinline__ unsigned pack_h2(float lo, float hi) {
    unsigned r;
    asm("cvt.rn.f16x2.f32 %0, %1, %2;" : "=r"(r) : "f"(hi), "f"(lo));
    return r;
}

__device__ __forceinline__ void cpa16(unsigned daddr, const void* src) {
    asm volatile("cp.async.cg.shared.global [%0], [%1], 16;" :: "r"(daddr), "l"(src));
}
__device__ __forceinline__ void cpcommit() {
    asm volatile("cp.async.commit_group;");
}
__device__ __forceinline__ void cpwait0() {
    asm volatile("cp.async.wait_group 0;");
}
__device__ __forceinline__ void cpwait1() {
    asm volatile("cp.async.wait_group 1;");
}

__device__ __forceinline__ void ldsm4(unsigned& r0, unsigned& r1, unsigned& r2, unsigned& r3, unsigned a) {
    asm volatile("ldmatrix.sync.aligned.m8n8.x4.shared.b16 {%0,%1,%2,%3},[%4];"
                 : "=r"(r0), "=r"(r1), "=r"(r2), "=r"(r3) : "r"(a));
}

__device__ __forceinline__ void ldsm4t(unsigned& r0, unsigned& r1, unsigned& r2, unsigned& r3, unsigned a) {
    asm volatile("ldmatrix.sync.aligned.m8n8.x4.trans.shared.b16 {%0,%1,%2,%3},[%4];"
                 : "=r"(r0), "=r"(r1), "=r"(r2), "=r"(r3) : "r"(a));
}

__device__ __forceinline__ void mma16(float* d,
                                      unsigned a0, unsigned a1, unsigned a2, unsigned a3,
                                      unsigned b0, unsigned b1) {
    asm volatile("mma.sync.aligned.m16n8k16.row.col.f32.f16.f16.f32 "
                 "{%0,%1,%2,%3},{%4,%5,%6,%7},{%8,%9},{%0,%1,%2,%3};"
                 : "+f"(d[0]), "+f"(d[1]), "+f"(d[2]), "+f"(d[3])
                 : "r"(a0), "r"(a1), "r"(a2), "r"(a3), "r"(b0), "r"(b1));
}

// ---------------------------------------------------------------------------
// fp32 -> fp16 pair conversion (with scale), vectorized by 4 floats.
// ---------------------------------------------------------------------------
__global__ __launch_bounds__(256) void conv_f2h(
    const float* __restrict__ in, unsigned* __restrict__ out, int n4, float scale)
{
    int i = blockIdx.x * 256 + threadIdx.x;
    if (i < n4) {
        float4 f = ((const float4*)in)[i];
        uint2 u;
        u.x = pack_h2(f.x * scale, f.y * scale);
        u.y = pack_h2(f.z * scale, f.w * scale);
        ((uint2*)out)[i] = u;
    }
}

// ---------------------------------------------------------------------------
// Stage one BK=64 slab of A and B into swizzled shared (cp.async, 8x16B/thread).
// ---------------------------------------------------------------------------
__device__ __forceinline__ void gemm_stage(
    unsigned sAb, unsigned sBb,
    const unsigned* __restrict__ Ap, const unsigned* __restrict__ Bp,
    int m0, int n0, int k0u, int tid)
{
    int tr = tid / 4;
    int tg = (tid % 4) * 2;
    for (int i = 0; i < 2; i++) {
        int row = tr + i * 64;
        int rx = row % 8;
        for (int j = 0; j < 2; j++) {
            int grp = tg + j;
            cpa16(sAb + (row * 32 + (grp ^ rx) * 4) * 4, Ap + (m0 + row) * 512 + k0u + grp * 4);
            cpa16(sBb + (row * 32 + (grp ^ rx) * 4) * 4, Bp + (n0 + row) * 512 + k0u + grp * 4);
        }
    }
}

// ---------------------------------------------------------------------------
// GEMM fp16 out: C[M, 2*Nu h] = A[M,1024] @ B[N,1024]^T. 2-stage cp.async.
// ---------------------------------------------------------------------------
__global__ __launch_bounds__(256) void gemm_hh_h(
    const unsigned* __restrict__ Ap, const unsigned* __restrict__ Bp,
    unsigned* __restrict__ Cp, int Nu)
{
    __shared__ unsigned As[2][128 * 32];
    __shared__ unsigned Bs[2][128 * 32];
    unsigned sA[2];
    unsigned sB[2];
    sA[0] = sptr(As[0]); sA[1] = sptr(As[1]);
    sB[0] = sptr(Bs[0]); sB[1] = sptr(Bs[1]);

    const int tid = threadIdx.x;
    const int lane = tid % 32;
    const int warp = tid / 32;
    const int gid = lane / 4;
    const int tig = lane % 4;
    const int wm = warp / 4;
    const int wn = warp % 4;
    const int m0 = blockIdx.y * 128;
    const int n0 = blockIdx.x * 128;

    const int arow = wm * 64 + (lane % 16);
    const int ga_add = lane / 16;
    const int brow = wn * 32 + ((lane / 16) % 2) * 8 + (lane % 8);
    const int gb_add = (lane / 8) % 2;

    float acc[4][4][4];
    for (int i = 0; i < 4; i++) {
        for (int j = 0; j < 4; j++) {
            for (int q = 0; q < 4; q++) { acc[i][j][q] = 0.f; }
        }
    }

    gemm_stage(sA[0], sB[0], Ap, Bp, m0, n0, 0, tid);
    cpcommit();
    gemm_stage(sA[1], sB[1], Ap, Bp, m0, n0, 32, tid);
    cpcommit();

    for (int kk = 0; kk < 16; kk++) {
        if (kk < 15) { cpwait1(); } else { cpwait0(); }
        __syncthreads();
        const unsigned cA = sA[kk % 2];
        const unsigned cB = sB[kk % 2];

        for (int ks = 0; ks < 4; ks++) {
            unsigned af[4][4];
            unsigned bf[2][4];
            for (int mt = 0; mt < 4; mt++) {
                int r = arow + mt * 16;
                int grp = (ks * 2 + ga_add) ^ (r % 8);
                ldsm4(af[mt][0], af[mt][1], af[mt][2], af[mt][3], cA + r * 128 + grp * 16);
            }
            for (int p = 0; p < 2; p++) {
                int r = brow + p * 16;
                int grp = (ks * 2 + gb_add) ^ (r % 8);
                ldsm4(bf[p][0], bf[p][1], bf[p][2], bf[p][3], cB + r * 128 + grp * 16);
            }
            for (int mt = 0; mt < 4; mt++) {
                for (int p = 0; p < 2; p++) {
                    mma16(acc[mt][2 * p + 0], af[mt][0], af[mt][1], af[mt][2], af[mt][3],
                          bf[p][0], bf[p][1]);
                    mma16(acc[mt][2 * p + 1], af[mt][0], af[mt][1], af[mt][2], af[mt][3],
                          bf[p][2], bf[p][3]);
                }
            }
        }
        __syncthreads();
        if (kk < 14) {
            gemm_stage(sA[kk % 2], sB[kk % 2], Ap, Bp, m0, n0, (kk + 2) * 32, tid);
            cpcommit();
        }
    }

    for (int mt = 0; mt < 4; mt++) {
        for (int nt = 0; nt < 4; nt++) {
            int row = m0 + wm * 64 + mt * 16 + gid;
            int colu = (n0 + wn * 32 + nt * 8 + 2 * tig) / 2;
            Cp[row * Nu + colu] = pack_h2(acc[mt][nt][0], acc[mt][nt][1]);
            Cp[(row + 8) * Nu + colu] = pack_h2(acc[mt][nt][2], acc[mt][nt][3]);
        }
    }
}

// ---------------------------------------------------------------------------
// GEMM fp32 out + bias (output projection). 2-stage cp.async.
// ---------------------------------------------------------------------------
__global__ __launch_bounds__(256) void gemm_hh_f(
    const unsigned* __restrict__ Ap, const unsigned* __restrict__ Bp,
    float* __restrict__ Cp, const float* __restrict__ bias)
{
    __shared__ unsigned As[2][128 * 32];
    __shared__ unsigned Bs[2][128 * 32];
    unsigned sA[2];
    unsigned sB[2];
    sA[0] = sptr(As[0]); sA[1] = sptr(As[1]);
    sB[0] = sptr(Bs[0]); sB[1] = sptr(Bs[1]);

    const int tid = threadIdx.x;
    const int lane = tid % 32;
    const int warp = tid / 32;
    const int gid = lane / 4;
    const int tig = lane % 4;
    const int wm = warp / 4;
    const int wn = warp % 4;
    const int m0 = blockIdx.y * 128;
    const int n0 = blockIdx.x * 128;

    const int arow = wm * 64 + (lane % 16);
    const int ga_add = lane / 16;
    const int brow = wn * 32 + ((lane / 16) % 2) * 8 + (lane % 8);
    const int gb_add = (lane / 8) % 2;

    float acc[4][4][4];
    for (int i = 0; i < 4; i++) {
        for (int j = 0; j < 4; j++) {
            for (int q = 0; q < 4; q++) { acc[i][j][q] = 0.f; }
        }
    }

    gemm_stage(sA[0], sB[0], Ap, Bp, m0, n0, 0, tid);
    cpcommit();
    gemm_stage(sA[1], sB[1], Ap, Bp, m0, n0, 32, tid);
    cpcommit();

    for (int kk = 0; kk < 16; kk++) {
        if (kk < 15) { cpwait1(); } else { cpwait0(); }
        __syncthreads();
        const unsigned cA = sA[kk % 2];
        const unsigned cB = sB[kk % 2];

        for (int ks = 0; ks < 4; ks++) {
            unsigned af[4][4];
            unsigned bf[2][4];
            for (int mt = 0; mt < 4; mt++) {
                int r = arow + mt * 16;
                int grp = (ks * 2 + ga_add) ^ (r % 8);
                ldsm4(af[mt][0], af[mt][1], af[mt][2], af[mt][3], cA + r * 128 + grp * 16);
            }
            for (int p = 0; p < 2; p++) {
                int r = brow + p * 16;
                int grp = (ks * 2 + gb_add) ^ (r % 8);
                ldsm4(bf[p][0], bf[p][1], bf[p][2], bf[p][3], cB + r * 128 + grp * 16);
            }
            for (int mt = 0; mt < 4; mt++) {
                for (int p = 0; p < 2; p++) {
                    mma16(acc[mt][2 * p + 0], af[mt][0], af[mt][1], af[mt][2], af[mt][3],
                          bf[p][0], bf[p][1]);
                    mma16(acc[mt][2 * p + 1], af[mt][0], af[mt][1], af[mt][2], af[mt][3],
                          bf[p][2], bf[p][3]);
                }
            }
        }
        __syncthreads();
        if (kk < 14) {
            gemm_stage(sA[kk % 2], sB[kk % 2], Ap, Bp, m0, n0, (kk + 2) * 32, tid);
            cpcommit();
        }
    }

    for (int mt = 0; mt < 4; mt++) {
        for (int nt = 0; nt < 4; nt++) {
            int row = m0 + wm * 64 + mt * 16 + gid;
            int col = n0 + wn * 32 + nt * 8 + 2 * tig;
            float bb0 = bias[col];
            float bb1 = bias[col + 1];
            *(float2*)(Cp + row * 1024 + col) =
                make_float2(acc[mt][nt][0] + bb0, acc[mt][nt][1] + bb1);
            *(float2*)(Cp + (row + 8) * 1024 + col) =
                make_float2(acc[mt][nt][2] + bb0, acc[mt][nt][3] + bb1);
        }
    }
}

// ---------------------------------------------------------------------------
// Flash attention: Br=128, 4 warps, 2-stage cp.async K/V pipeline.
// KV rows are combined: row = [k0..k127 | v0..v127] uints (stride 256).
// ---------------------------------------------------------------------------
__device__ __forceinline__ void kv_stage(
    unsigned sKb, unsigned sVb, const unsigned* __restrict__ kvrow0, int kt, int tid)
{
    int r = tid / 2;
    int rx = r % 8;
    const unsigned* src = kvrow0 + (kt * 64 + r) * 256;
    for (int j = 0; j < 4; j++) {
        int grp = j * 2 + (tid % 2);
        unsigned sw = (unsigned)((grp ^ rx) * 16);
        cpa16(sKb + r * 128 + sw, src + grp * 4);
        cpa16(sVb + r * 128 + sw, src + 128 + grp * 4);
    }
}

__global__ __launch_bounds__(128) void attn_h(
    const unsigned* __restrict__ qbuf, const unsigned* __restrict__ kvbuf,
    unsigned* __restrict__ obuf)
{
    __shared__ unsigned Qs[128 * 32];
    __shared__ unsigned Ks[2][64 * 32];
    __shared__ unsigned Vs[2][64 * 32];
    const unsigned sQ = sptr(Qs);
    unsigned sK[2];
    unsigned sV[2];
    sK[0] = sptr(Ks[0]); sK[1] = sptr(Ks[1]);
    sV[0] = sptr(Vs[0]); sV[1] = sptr(Vs[1]);

    const int tid = threadIdx.x;
    const int lane = tid % 32;
    const int warp = tid / 32;
    const int gid = lane / 4;
    const int tig = lane % 4;
    const int q0 = blockIdx.x * 128;
    const int bh = blockIdx.y;
    const int bb = bh / 16;
    const int hh = bh % 16;
    const int gg = hh / 4;

    const int kmax = q0 / 64 + 1;
    const unsigned* kvrow0 = kvbuf + (size_t)bb * TT * 256 + gg * 32;

    kv_stage(sK[0], sV[0], kvrow0, 0, tid);
    cpcommit();
    kv_stage(sK[1], sV[1], kvrow0, 1, tid);
    cpcommit();

    // Stage Q (plain stores; overlaps with the cp.asyncs above).
    {
        const unsigned* srow = qbuf + (bb * TT + q0 + tid) * 512 + hh * 32;
        unsigned* drow = Qs + tid * 32;
        int rx = tid % 8;
        for (int grp = 0; grp < 8; grp++) {
            *(uint4*)(drow + (grp ^ rx) * 4) = *(const uint4*)(srow + grp * 4);
        }
    }
    __syncthreads();

    unsigned qf[2][4][4];
    const int qga = lane / 16;
    for (int mt = 0; mt < 2; mt++) {
        int qrow = warp * 32 + mt * 16 + (lane % 16);
        for (int ks = 0; ks < 4; ks++) {
            int grp = (ks * 2 + qga) ^ (qrow % 8);
            ldsm4(qf[mt][ks][0], qf[mt][ks][1], qf[mt][ks][2], qf[mt][ks][3],
                  sQ + qrow * 128 + grp * 16);
        }
    }

    float oacc[2][8][4];
    for (int mt = 0; mt < 2; mt++) {
        for (int nt = 0; nt < 8; nt++) {
            for (int q = 0; q < 4; q++) { oacc[mt][nt][q] = 0.f; }
        }
    }
    float mr[2][2];
    float lr[2][2];
    for (int mt = 0; mt < 2; mt++) {
        mr[mt][0] = -1e30f; mr[mt][1] = -1e30f;
        lr[mt][0] = 0.f; lr[mt][1] = 0.f;
    }

    const int rw0 = q0 + warp * 32;

    const int s_nadd = ((lane / 16) % 2) * 8 + (lane % 8);
    const int s_gadd = (lane / 8) % 2;
    const int v_kadd = ((lane / 8) % 2) * 8 + (lane % 8);
    const int v_gadd = (lane / 16) % 2;

    for (int kt = 0; kt <= kmax; kt++) {
        if (kt < kmax) { cpwait1(); } else { cpwait0(); }
        __syncthreads();
        const unsigned cK = sK[kt % 2];
        const unsigned cV = sV[kt % 2];

        if (kt * 64 <= rw0 + 31) {   // warp not fully masked
            float sc[2][8][4];
            for (int mt = 0; mt < 2; mt++) {
                for (int nt = 0; nt < 8; nt++) {
                    for (int q = 0; q < 4; q++) { sc[mt][nt][q] = 0.f; }
                }
            }
            for (int ks = 0; ks < 4; ks++) {
                for (int p = 0; p < 4; p++) {
                    int nrow = p * 16 + s_nadd;
                    int grp = (ks * 2 + s_gadd) ^ (nrow % 8);
                    unsigned kf0, kf1, kf2, kf3;
                    ldsm4(kf0, kf1, kf2, kf3, cK + nrow * 128 + grp * 16);
                    for (int mt = 0; mt < 2; mt++) {
                        mma16(sc[mt][2 * p + 0], qf[mt][ks][0], qf[mt][ks][1], qf[mt][ks][2], qf[mt][ks][3], kf0, kf1);
                        mma16(sc[mt][2 * p + 1], qf[mt][ks][0], qf[mt][ks][1], qf[mt][ks][2], qf[mt][ks][3], kf2, kf3);
                    }
                }
            }

            if (kt * 64 + 63 > rw0) {
                for (int mt = 0; mt < 2; mt++) {
                    int rowA = rw0 + mt * 16 + gid;
                    int rowB = rowA + 8;
                    for (int nt = 0; nt < 8; nt++) {
                        int kcol = kt * 64 + nt * 8 + 2 * tig;
                        if (kcol > rowA) { sc[mt][nt][0] = -1e30f; }
                        if (kcol + 1 > rowA) { sc[mt][nt][1] = -1e30f; }
                        if (kcol > rowB) { sc[mt][nt][2] = -1e30f; }
                        if (kcol + 1 > rowB) { sc[mt][nt][3] = -1e30f; }
                    }
                }
            }

            for (int mt = 0; mt < 2; mt++) {
                float mt0 = -1e30f;
                float mt1 = -1e30f;
                for (int nt = 0; nt < 8; nt++) {
                    mt0 = fmaxf(mt0, fmaxf(sc[mt][nt][0], sc[mt][nt][1]));
                    mt1 = fmaxf(mt1, fmaxf(sc[mt][nt][2], sc[mt][nt][3]));
                }
                mt0 = fmaxf(mt0, __shfl_xor_sync(0xffffffffu, mt0, 1));
                mt0 = fmaxf(mt0, __shfl_xor_sync(0xffffffffu, mt0, 2));
                mt1 = fmaxf(mt1, __shfl_xor_sync(0xffffffffu, mt1, 1));
                mt1 = fmaxf(mt1, __shfl_xor_sync(0xffffffffu, mt1, 2));
                float mn0 = fmaxf(mr[mt][0], mt0);
                float mn1 = fmaxf(mr[mt][1], mt1);
                float c0 = __expf(mr[mt][0] - mn0);
                float c1 = __expf(mr[mt][1] - mn1);
                float ps0 = 0.f;
                float ps1 = 0.f;
                for (int nt = 0; nt < 8; nt++) {
                    sc[mt][nt][0] = __expf(sc[mt][nt][0] - mn0);
                    sc[mt][nt][1] = __expf(sc[mt][nt][1] - mn0);
                    sc[mt][nt][2] = __expf(sc[mt][nt][2] - mn1);
                    sc[mt][nt][3] = __expf(sc[mt][nt][3] - mn1);
                    ps0 += sc[mt][nt][0] + sc[mt][nt][1];
                    ps1 += sc[mt][nt][2] + sc[mt][nt][3];
                    oacc[mt][nt][0] *= c0;
                    oacc[mt][nt][1] *= c0;
                    oacc[mt][nt][2] *= c1;
                    oacc[mt][nt][3] *= c1;
                }
                ps0 += __shfl_xor_sync(0xffffffffu, ps0, 1);
                ps0 += __shfl_xor_sync(0xffffffffu, ps0, 2);
                ps1 += __shfl_xor_sync(0xffffffffu, ps1, 1);
                ps1 += __shfl_xor_sync(0xffffffffu, ps1, 2);
                lr[mt][0] = lr[mt][0] * c0 + ps0;
                lr[mt][1] = lr[mt][1] * c1 + ps1;
                mr[mt][0] = mn0;
                mr[mt][1] = mn1;
            }

            for (int ks = 0; ks < 4; ks++) {
                unsigned pf[2][4];
                for (int mt = 0; mt < 2; mt++) {
                    pf[mt][0] = pack_h2(sc[mt][2 * ks + 0][0], sc[mt][2 * ks + 0][1]);
                    pf[mt][1] = pack_h2(sc[mt][2 * ks + 0][2], sc[mt][2 * ks + 0][3]);
                    pf[mt][2] = pack_h2(sc[mt][2 * ks + 1][0], sc[mt][2 * ks + 1][1]);
                    pf[mt][3] = pack_h2(sc[mt][2 * ks + 1][2], sc[mt][2 * ks + 1][3]);
                }
                for (int p = 0; p < 4; p++) {
                    int krow = ks * 16 + v_kadd;
                    int grp = (p * 2 + v_gadd) ^ (krow % 8);
                    unsigned vf0, vf1, vf2, vf3;
                    ldsm4t(vf0, vf1, vf2, vf3, cV + krow * 128 + grp * 16);
                    for (int mt = 0; mt < 2; mt++) {
                        mma16(oacc[mt][2 * p + 0], pf[mt][0], pf[mt][1], pf[mt][2], pf[mt][3], vf0, vf1);
                        mma16(oacc[mt][2 * p + 1], pf[mt][0], pf[mt][1], pf[mt][2], pf[mt][3], vf2, vf3);
                    }
                }
            }
        }

        __syncthreads();
        if (kt + 2 <= kmax) {
            kv_stage(sK[kt % 2], sV[kt % 2], kvrow0, kt + 2, tid);
            cpcommit();
        }
    }

    for (int mt = 0; mt < 2; mt++) {
        float i0 = 1.f / lr[mt][0];
        float i1 = 1.f / lr[mt][1];
        int rowA = rw0 + mt * 16 + gid;
        int rowB = rowA + 8;
        for (int nt = 0; nt < 8; nt++) {
            int colu = hh * 32 + nt * 4 + tig;
            obuf[(bb * TT + rowA) * 512 + colu] = pack_h2(oacc[mt][nt][0] * i0, oacc[mt][nt][1] * i0);
            obuf[(bb * TT + rowB) * 512 + colu] = pack_h2(oacc[mt][nt][2] * i1, oacc[mt][nt][3] * i1);
        }
    }
}

extern "C" void kernel_launch(void* const* d_in, const int* in_sizes, int n_in,
                              void* d_out, int out_size)
{
    const float* x  = (const float*)d_in[0];
    const float* Wq = (const float*)d_in[1];
    const float* Wk = (const float*)d_in[2];
    const float* Wv = (const float*)d_in[3];
    const float* Wp = (const float*)d_in[4];
    const float* bp = (const float*)d_in[5];
    float* out = (float*)d_out;

    unsigned* gx = 0;
    unsigned* gwq = 0;
    unsigned* gwkv = 0;
    unsigned* gwp = 0;
    unsigned* gq = 0;
    unsigned* gkv = 0;
    unsigned* ga = 0;
    cudaGetSymbolAddress((void**)&gx, g_x);
    cudaGetSymbolAddress((void**)&gwq, g_wq);
    cudaGetSymbolAddress((void**)&gwkv, g_wkv);
    cudaGetSymbolAddress((void**)&gwp, g_wp);
    cudaGetSymbolAddress((void**)&gq, g_q);
    cudaGetSymbolAddress((void**)&gkv, g_kv);
    cudaGetSymbolAddress((void**)&ga, g_attn);

    conv_f2h<<<8192, 256>>>(x, gx, 2097152, 1.f);
    conv_f2h<<<1024, 256>>>(Wq, gwq, 262144, 0.125f);
    conv_f2h<<<256, 256>>>(Wk, gwkv, 65536, 1.f);
    conv_f2h<<<256, 256>>>(Wv, gwkv + 256 * 512, 65536, 1.f);
    conv_f2h<<<1024, 256>>>(Wp, gwp, 262144, 1.f);

    gemm_hh_h<<<dim3(8, 64), 256>>>(gx, gwq, gq, 512);
    gemm_hh_h<<<dim3(4, 64), 256>>>(gx, gwkv, gkv, 256);

    attn_h<<<dim3(16, 64), 128>>>(gq, gkv, ga);

    gemm_hh_f<<<dim3(8, 64), 256>>>(ga, gwp, out, bp);
}